// round 6
// baseline (speedup 1.0000x reference)
#include <cuda_runtime.h>
#include <cstdint>
#include <math.h>

#define NBINS 15
#define C_DIM 1000
#define ROW_BYTES 4000
#define C4    250               // float4 per row
#define CHUNK_ROWS 4
#define CHUNK_BYTES (CHUNK_ROWS * ROW_BYTES)   // 16000
#define STAGES 3
#define THREADS 128             // 4 warps: warp w consumes row w of a chunk
#define GRID_BLOCKS 608         // 152 SMs x 4 CTAs (smem-limited)

// Global accumulators (allocation-free scratch). Zeroed at module load for the
// first (correctness) call; the finishing block resets them for each replay.
__device__ double g_cnt[NBINS];
__device__ double g_conf[NBINS];
__device__ double g_acc[NBINS];
__device__ unsigned int g_ticket = 0;

__device__ __forceinline__ float ex2f(float x) {
    float r;
    asm("ex2.approx.f32 %0, %1;" : "=f"(r) : "f"(x));
    return r;
}
__device__ __forceinline__ unsigned f2ord(float f) {
    int i = __float_as_int(f);
    return (unsigned)(i ^ ((i >> 31) | 0x80000000));
}
__device__ __forceinline__ float ord2f(unsigned u) {
    int i = (int)(u ^ ((((int)~u) >> 31) | 0x80000000));
    return __int_as_float(i);
}

__device__ __forceinline__ unsigned int smem_u32(const void* p) {
    unsigned int a;
    asm("{ .reg .u64 t; cvta.to.shared.u64 t, %1; cvt.u32.u64 %0, t; }" : "=r"(a) : "l"(p));
    return a;
}
__device__ __forceinline__ void mbar_init(unsigned int a, unsigned int cnt) {
    asm volatile("mbarrier.init.shared.b64 [%0], %1;" :: "r"(a), "r"(cnt) : "memory");
}
__device__ __forceinline__ void mbar_expect_tx(unsigned int a, unsigned int bytes) {
    asm volatile("mbarrier.arrive.expect_tx.shared.b64 _, [%0], %1;" :: "r"(a), "r"(bytes) : "memory");
}
__device__ __forceinline__ void bulk_g2s(unsigned int dst, const void* src,
                                         unsigned int bytes, unsigned int mbar) {
    asm volatile(
        "cp.async.bulk.shared::cluster.global.mbarrier::complete_tx::bytes [%0], [%1], %2, [%3];"
        :: "r"(dst), "l"(src), "r"(bytes), "r"(mbar) : "memory");
}
__device__ __forceinline__ void mbar_wait(unsigned int a, unsigned int parity) {
    unsigned int done;
    asm volatile(
        "{ .reg .pred p;\n"
        "  mbarrier.try_wait.parity.acquire.cta.shared::cta.b64 p, [%1], %2;\n"
        "  selp.b32 %0, 1, 0, p; }"
        : "=r"(done) : "r"(a), "r"(parity) : "memory");
    if (!done) {
        asm volatile(
            "{ .reg .pred P;\n"
            "W_%=:\n"
            "  mbarrier.try_wait.parity.acquire.cta.shared::cta.b64 P, [%0], %1, 0x989680;\n"
            "  @P bra.uni D_%=;\n"
            "  bra.uni W_%=;\n"
            "D_%=: }"
            :: "r"(a), "r"(parity) : "memory");
    }
}

__global__ __launch_bounds__(THREADS) void ece_tma_kernel(
    const float* __restrict__ logits,
    const int* __restrict__ labels,
    int n_rows,
    float* __restrict__ out)
{
    __shared__ __align__(128) char tile[STAGES][CHUNK_BYTES];
    __shared__ unsigned long long mbar[STAGES];
    __shared__ float s_cnt[NBINS];
    __shared__ float s_conf[NBINS];
    __shared__ float s_acc[NBINS];
    __shared__ bool  s_is_last;

    const int tid  = threadIdx.x;
    const int lane = tid & 31;
    const int warp = tid >> 5;

    if (tid < NBINS) {
        s_cnt[tid]  = 0.0f;
        s_conf[tid] = 0.0f;
        s_acc[tid]  = 0.0f;
    }
    if (tid == 0) {
        #pragma unroll
        for (int s = 0; s < STAGES; s++)
            mbar_init(smem_u32(&mbar[s]), 1u);
    }
    __syncthreads();

    const int n_chunks = (n_rows + CHUNK_ROWS - 1) / CHUNK_ROWS;
    // Block b handles chunks b, b+grid, ... -> local iteration i maps to
    // chunk = blockIdx.x + i*gridDim.x.
    const int my_chunks = (n_chunks - blockIdx.x + (int)gridDim.x - 1) / (int)gridDim.x;

    // Prologue: fill the pipeline.
    if (tid == 0) {
        #pragma unroll
        for (int i = 0; i < STAGES; i++) {
            if (i < my_chunks) {
                int chunk = blockIdx.x + i * gridDim.x;
                int row0  = chunk * CHUNK_ROWS;
                int rows  = min(CHUNK_ROWS, n_rows - row0);
                unsigned int bytes = (unsigned int)rows * ROW_BYTES;
                unsigned int mb = smem_u32(&mbar[i]);
                mbar_expect_tx(mb, bytes);
                bulk_g2s(smem_u32(&tile[i][0]), logits + (size_t)row0 * C_DIM, bytes, mb);
            }
        }
    }

    for (int i = 0; i < my_chunks; i++) {
        const int stage = i % STAGES;
        const unsigned int parity = (unsigned)(i / STAGES) & 1u;
        const int chunk = blockIdx.x + i * gridDim.x;
        const int row   = chunk * CHUNK_ROWS + warp;

        mbar_wait(smem_u32(&mbar[stage]), parity);

        if (row < n_rows) {
            const float4* rp = reinterpret_cast<const float4*>(&tile[stage][warp * ROW_BYTES]) + lane;
            float4 v[8];
            #pragma unroll
            for (int k = 0; k < 8; k++) {
                if (lane + 32 * k < C4) v[k] = rp[32 * k];
                else v[k] = make_float4(-1e30f, -1e30f, -1e30f, -1e30f);
            }

            // Per-float4 maxes, tree to lane max, warp max via integer redux.
            float m4[8];
            #pragma unroll
            for (int k = 0; k < 8; k++)
                m4[k] = fmaxf(fmaxf(v[k].x, v[k].y), fmaxf(v[k].z, v[k].w));
            float a0 = fmaxf(m4[0], m4[1]), a1 = fmaxf(m4[2], m4[3]);
            float a2 = fmaxf(m4[4], m4[5]), a3 = fmaxf(m4[6], m4[7]);
            float m  = fmaxf(fmaxf(a0, a1), fmaxf(a2, a3));
            float wm = ord2f(__reduce_max_sync(0xffffffffu, f2ord(m)));

            // Argmax drill-down: smallest index equal to wm.
            int mi = 0x7fffffff;
            #pragma unroll
            for (int k = 7; k >= 0; k--) {
                if (m4[k] == wm) {
                    int base = 4 * (lane + 32 * k);
                    if (v[k].w == wm) mi = base + 3;
                    if (v[k].z == wm) mi = base + 2;
                    if (v[k].y == wm) mi = base + 1;
                    if (v[k].x == wm) mi = base;
                }
            }
            unsigned wmi = __reduce_min_sync(0xffffffffu, (unsigned)mi);

            // sum exp(x - wm) = 2^(x*log2e + b); padding underflows to 0.
            const float L = 1.4426950408889634f;
            const float b = -wm * L;
            float s0 = 0.f, s1 = 0.f, s2 = 0.f, s3 = 0.f;
            #pragma unroll
            for (int k = 0; k < 8; k++) {
                s0 += ex2f(fmaf(v[k].x, L, b));
                s1 += ex2f(fmaf(v[k].y, L, b));
                s2 += ex2f(fmaf(v[k].z, L, b));
                s3 += ex2f(fmaf(v[k].w, L, b));
            }
            float s = (s0 + s1) + (s2 + s3);
            #pragma unroll
            for (int off = 16; off; off >>= 1)
                s += __shfl_xor_sync(0xffffffffu, s, off);

            if (lane == 0) {
                float conf = 1.0f / s;   // = exp(wm - lse), > 0 so valid=1
                int bin = 0;
                #pragma unroll
                for (int q = 1; q < NBINS; q++)
                    bin += (conf > ((float)q / (float)NBINS)) ? 1 : 0;
                float acc = (labels[row] == (int)wmi) ? 1.0f : 0.0f;
                atomicAdd(&s_cnt[bin],  1.0f);
                atomicAdd(&s_conf[bin], conf);
                atomicAdd(&s_acc[bin],  acc);
            }
        }

        __syncthreads();   // all warps done with this stage -> safe to refill

        if (tid == 0) {
            int ni = i + STAGES;
            if (ni < my_chunks) {
                int nchunk = blockIdx.x + ni * gridDim.x;
                int row0   = nchunk * CHUNK_ROWS;
                int rows   = min(CHUNK_ROWS, n_rows - row0);
                unsigned int bytes = (unsigned int)rows * ROW_BYTES;
                unsigned int mb = smem_u32(&mbar[stage]);
                mbar_expect_tx(mb, bytes);
                bulk_g2s(smem_u32(&tile[stage][0]), logits + (size_t)row0 * C_DIM, bytes, mb);
            }
        }
    }

    __syncthreads();
    if (tid < NBINS) {
        float c = s_cnt[tid];
        if (c != 0.0f) {
            atomicAdd(&g_cnt[tid],  (double)c);
            atomicAdd(&g_conf[tid], (double)s_conf[tid]);
            atomicAdd(&g_acc[tid],  (double)s_acc[tid]);
        }
    }

    // Last-block-done ticket -> fused finalize + reset for graph replays.
    __threadfence();
    __syncthreads();
    if (tid == 0) {
        unsigned int t = atomicAdd(&g_ticket, 1u);
        s_is_last = (t == gridDim.x - 1);
    }
    __syncthreads();

    if (s_is_last && warp == 0) {
        double term_ece = 0.0, term_acc = 0.0;
        if (lane < NBINS) {
            double cnt = g_cnt[lane];
            if (cnt > 0.0) {
                double prop = cnt / (double)n_rows;
                double avg_conf = g_conf[lane] / cnt;
                double avg_acc  = g_acc[lane]  / cnt;
                term_ece = fabs(avg_conf - avg_acc) * prop;
                term_acc = avg_acc * prop;
            }
            g_cnt[lane]  = 0.0;
            g_conf[lane] = 0.0;
            g_acc[lane]  = 0.0;
        }
        #pragma unroll
        for (int off = 16; off; off >>= 1) {
            term_ece += __shfl_xor_sync(0xffffffffu, term_ece, off);
            term_acc += __shfl_xor_sync(0xffffffffu, term_acc, off);
        }
        if (lane == 0) {
            out[0] = (float)(term_ece * 100.0);
            out[1] = (float)(term_acc * 100.0);
            g_ticket = 0;
        }
    }
}

extern "C" void kernel_launch(void* const* d_in, const int* in_sizes, int n_in,
                              void* d_out, int out_size) {
    const float* logits = (const float*)d_in[0];
    const int*   labels = (const int*)d_in[1];
    float* out = (float*)d_out;

    int n_rows = in_sizes[1];  // labels element count = N

    ece_tma_kernel<<<GRID_BLOCKS, THREADS>>>(logits, labels, n_rows, out);
}